// round 16
// baseline (speedup 1.0000x reference)
#include <cuda_runtime.h>

#define BB 8
#define LL 512
#define DD 128

typedef unsigned long long ull;

// Scratch (allocation-free rule: __device__ globals)
__device__ float g_eq[BB * DD * LL];  // [b][d][l]  e^{2q}, l contiguous
__device__ float g_ek[BB * LL * DD];  // [b][l][d]  e^{2k}

// ---- packed f32x2 helpers (sm_100a) ----
__device__ __forceinline__ ull fma2(ull a, ull b, ull c) {
    ull d; asm("fma.rn.f32x2 %0, %1, %2, %3;" : "=l"(d) : "l"(a), "l"(b), "l"(c)); return d;
}
__device__ __forceinline__ ull mul2(ull a, ull b) {
    ull d; asm("mul.rn.f32x2 %0, %1, %2;" : "=l"(d) : "l"(a), "l"(b)); return d;
}
__device__ __forceinline__ ull rcp2(ull x) {   // rcp of both packed halves
    ull y;
    asm("{\n\t.reg .f32 lo, hi;\n\t"
        "mov.b64 {lo, hi}, %1;\n\t"
        "rcp.approx.f32 lo, lo;\n\t"
        "rcp.approx.f32 hi, hi;\n\t"
        "mov.b64 %0, {lo, hi};\n\t}"
        : "=l"(y) : "l"(x));
    return y;
}
__device__ __forceinline__ ull dup_f32(float v) {
    ull d; asm("mov.b64 %0, {%1, %1};" : "=l"(d) : "f"(v)); return d;
}

#define ONE2 0x3F8000003F800000ULL

// ---------------------------------------------------------------------------
// Kernel A: Eq = exp(2 * inp@u_w^T) stored transposed [b][d][l],
//           Ek = exp(2 * inp@v_w^T) row-major [b][l][d]
// ---------------------------------------------------------------------------
__global__ __launch_bounds__(512, 2) void proj_kernel(
    const float* __restrict__ inp,
    const float* __restrict__ uw,
    const float* __restrict__ vw)
{
    __shared__ float xS[32][32];
    __shared__ float wuS[128][33];
    __shared__ float wvS[128][33];

    const int b    = blockIdx.x >> 4;
    const int l0   = (blockIdx.x & 15) << 5;   // 32 rows per block
    const int t    = threadIdx.x;
    const int lane = t & 31;
    const int warp = t >> 5;
    const int lrow = warp << 1;                // 2 rows per thread (16 warps)

    float qacc[2][4], kacc[2][4];
#pragma unroll
    for (int i = 0; i < 2; i++)
#pragma unroll
        for (int jj = 0; jj < 4; jj++) { qacc[i][jj] = 0.f; kacc[i][jj] = 0.f; }

    for (int kc = 0; kc < 4; kc++) {
        const int d0 = kc << 5;
        for (int idx = t; idx < 32 * 32; idx += 512) {
            int r = idx >> 5, c = idx & 31;
            xS[r][c] = inp[(b * LL + l0 + r) * DD + d0 + c];
        }
        for (int idx = t; idx < 128 * 32; idx += 512) {
            int r = idx >> 5, c = idx & 31;
            wuS[r][c] = uw[r * DD + d0 + c];
            wvS[r][c] = vw[r * DD + d0 + c];
        }
        __syncthreads();

#pragma unroll 8
        for (int d = 0; d < 32; d++) {
            const float x0 = xS[lrow + 0][d];
            const float x1 = xS[lrow + 1][d];
#pragma unroll
            for (int jj = 0; jj < 4; jj++) {
                const int e = lane + (jj << 5);
                const float wu = wuS[e][d];
                const float wv = wvS[e][d];
                qacc[0][jj] = fmaf(x0, wu, qacc[0][jj]);
                qacc[1][jj] = fmaf(x1, wu, qacc[1][jj]);
                kacc[0][jj] = fmaf(x0, wv, kacc[0][jj]);
                kacc[1][jj] = fmaf(x1, wv, kacc[1][jj]);
            }
        }
        __syncthreads();
    }

#pragma unroll
    for (int jj = 0; jj < 4; jj++) {
        const int e = lane + (jj << 5);
#pragma unroll
        for (int i = 0; i < 2; i++) {
            const int l = l0 + lrow + i;
            g_eq[((size_t)b * DD + e) * LL + l] = __expf(2.0f * qacc[i][jj]);
            g_ek[((size_t)b * LL + l) * DD + e] = __expf(2.0f * kacc[i][jj]);
        }
    }
}

// ---------------------------------------------------------------------------
// Kernel B: fused score + softmax + attn-write + out GEMM.
// Phase 2: packed f32x2 over j-pairs, ONE rcp per EIGHT d's (oct combine):
//   pairs (t_k, p_k) -> quads (n01,d01),(n23,d23) -> oct num/den -> rcp.
//   i-rows processed in two passes of 4 (register pressure control).
// Phase 4: packed f32x2 over d, 2x-dedup inp reads.
// ---------------------------------------------------------------------------
__global__ __launch_bounds__(512, 2) void attn_kernel(
    const float* __restrict__ inp,
    const float* __restrict__ aw,
    float* __restrict__ out,
    float* __restrict__ attn)
{
    union U {
        struct {                        // alive through phase 3
            ulonglong2 ekD[8][64];      // Ek dup'd: [ii][d/2] = (dup d, dup d+1)
            ulonglong2 naD[64];         // -a dup'd pairs
            float scp1[8][512];         // h=1 partial scores
        } p2;
        float red[4][2][4][DD];         // phase 4 partials (overlays p2)
    };
    __shared__ __align__(16) U u;
    __shared__ float sc[8][512];        // h=0 partials -> attn weights

    const int b    = blockIdx.x >> 6;
    const int i0   = (blockIdx.x & 63) << 3;
    const int t    = threadIdx.x;
    const int lane = t & 31;
    const int w    = t >> 5;

    // Stage Ek (duplicated pairs) and -a (duplicated pairs)
    {
        const float* __restrict__ ekbase = g_ek + ((size_t)b * LL + i0) * DD;
        for (int idx = t; idx < 8 * 64; idx += 512) {
            const int ii = idx >> 6, dp = idx & 63;
            const float2 kv = *(const float2*)(ekbase + ii * DD + (dp << 1));
            u.p2.ekD[ii][dp] = make_ulonglong2(dup_f32(kv.x), dup_f32(kv.y));
        }
    }
    if (t < 64) {
        const float2 a2 = ((const float2*)aw)[t];
        u.p2.naD[t] = make_ulonglong2(dup_f32(-a2.x), dup_f32(-a2.y));
    }
    __syncthreads();

    // ---- Phase 2: partial -sum_d a_d/(Eq*Ek+1) over this warp's d-half ----
    const int h     = w >> 3;            // d-half
    const int jc    = w & 7;             // 64-j tile
    const int jb    = jc << 6;
    const int dbase = h << 6;

    // float2 view of g_eq: row d has LL/2 float2s; lane owns pair (jb+2*lane)
    const float2* __restrict__ eqp2 =
        (const float2*)g_eq + (size_t)b * DD * (LL >> 1) + (jb >> 1) + lane;

    float (* __restrict__ dst)[512] = (h == 0) ? sc : u.p2.scp1;
    const int jst = jb + (lane << 1);

#pragma unroll 1
    for (int iig = 0; iig < 2; iig++) {   // i-rows in two passes of 4
        ull acc2[4];
#pragma unroll
        for (int k = 0; k < 4; k++) acc2[k] = 0ULL;

#pragma unroll 1
        for (int p = 0; p < 8; p++) {     // 8 octs over this warp's 64 d's
            const int d0 = dbase + (p << 3);
            ull eq[8];
#pragma unroll
            for (int i = 0; i < 8; i++)
                eq[i] = *(const ull*)(eqp2 + (size_t)(d0 + i) * (LL >> 1));
            const ulonglong2 na0 = u.p2.naD[(d0 >> 1) + 0];  // LDS.128 broadcast
            const ulonglong2 na1 = u.p2.naD[(d0 >> 1) + 1];
            const ulonglong2 na2 = u.p2.naD[(d0 >> 1) + 2];
            const ulonglong2 na3 = u.p2.naD[(d0 >> 1) + 3];
#pragma unroll
            for (int k = 0; k < 4; k++) {
                const int ii = (iig << 2) + k;
                const ulonglong2 ekA = u.p2.ekD[ii][(d0 >> 1) + 0];  // LDS.128
                const ulonglong2 ekB = u.p2.ekD[ii][(d0 >> 1) + 1];
                const ulonglong2 ekC = u.p2.ekD[ii][(d0 >> 1) + 2];
                const ulonglong2 ekD = u.p2.ekD[ii][(d0 >> 1) + 3];
                const ull x0 = fma2(eq[0], ekA.x, ONE2);
                const ull x1 = fma2(eq[1], ekA.y, ONE2);
                const ull x2 = fma2(eq[2], ekB.x, ONE2);
                const ull x3 = fma2(eq[3], ekB.y, ONE2);
                const ull x4 = fma2(eq[4], ekC.x, ONE2);
                const ull x5 = fma2(eq[5], ekC.y, ONE2);
                const ull x6 = fma2(eq[6], ekD.x, ONE2);
                const ull x7 = fma2(eq[7], ekD.y, ONE2);
                // pair numerators (carry -a) and denominators
                ull t0 = mul2(na0.x, x1); t0 = fma2(na0.y, x0, t0);
                ull t1 = mul2(na1.x, x3); t1 = fma2(na1.y, x2, t1);
                ull t2 = mul2(na2.x, x5); t2 = fma2(na2.y, x4, t2);
                ull t3 = mul2(na3.x, x7); t3 = fma2(na3.y, x6, t3);
                const ull p0 = mul2(x0, x1);
                const ull p1 = mul2(x2, x3);
                const ull p2 = mul2(x4, x5);
                const ull p3 = mul2(x6, x7);
                // quads
                ull n01 = mul2(t0, p1); n01 = fma2(t1, p0, n01);
                ull n23 = mul2(t2, p3); n23 = fma2(t3, p2, n23);
                const ull d01 = mul2(p0, p1);
                const ull d23 = mul2(p2, p3);
                // oct: one rcp per 8 d's
                ull num = mul2(n01, d23); num = fma2(n23, d01, num);
                const ull den = mul2(d01, d23);
                const ull r   = rcp2(den);
                acc2[k] = fma2(num, r, acc2[k]);
            }
        }
#pragma unroll
        for (int k = 0; k < 4; k++)
            *(ull*)&dst[(iig << 2) + k][jst] = acc2[k];   // STS.64
    }
    __syncthreads();

    // ---- Phase 3: softmax over j (score = 2*(sc + scp1) + const) ----
    if (w < 8) {
        const int r = w;
        float v[16];
        float mx = -1e30f;
#pragma unroll
        for (int q = 0; q < 16; q++) {
            const int jj = lane + (q << 5);
            v[q] = 2.0f * (sc[r][jj] + u.p2.scp1[r][jj]);
            mx = fmaxf(mx, v[q]);
        }
#pragma unroll
        for (int o = 16; o > 0; o >>= 1) mx = fmaxf(mx, __shfl_xor_sync(0xffffffffu, mx, o));
        float s = 0.f;
#pragma unroll
        for (int q = 0; q < 16; q++) { v[q] = __expf(v[q] - mx); s += v[q]; }
#pragma unroll
        for (int o = 16; o > 0; o >>= 1) s += __shfl_xor_sync(0xffffffffu, s, o);
        const float inv = 1.0f / s;
        float* arow = attn + ((size_t)b * LL + i0 + r) * LL;
#pragma unroll
        for (int q = 0; q < 16; q++) {
            const int jj = lane + (q << 5);
            const float av = v[q] * inv;
            sc[r][jj] = av;       // reuse for phase 4
            arow[jj]  = av;       // coalesced attn output
        }
    }
    __syncthreads();   // scp1/staging dead beyond this point -> red may overlay

    // ---- Phase 4a: packed-d partial out over 64 j's for 4 i-rows per warp --
    const int ig = w >> 3;   // i-group: rows ig*4 .. ig*4+3
    const int cjc = w & 7;   // j-chunk: [cjc*64, cjc*64+64)
    {
        ull accA[4], accB[4];  // per i-row: (d0,d1) and (d2,d3) of lane's 4 d's
#pragma unroll
        for (int i = 0; i < 4; i++) { accA[i] = 0ULL; accB[i] = 0ULL; }

        const ull* __restrict__ xin =
            (const ull*)(inp + ((size_t)b * LL + (cjc << 6)) * DD) + (lane << 1);
        const float2* __restrict__ s0 = (const float2*)&sc[(ig << 2) + 0][cjc << 6];
        const float2* __restrict__ s1 = (const float2*)&sc[(ig << 2) + 1][cjc << 6];
        const float2* __restrict__ s2 = (const float2*)&sc[(ig << 2) + 2][cjc << 6];
        const float2* __restrict__ s3 = (const float2*)&sc[(ig << 2) + 3][cjc << 6];
#pragma unroll 4
        for (int jj = 0; jj < 32; jj++) {
            const float2 w0 = s0[jj];               // (w_{2jj}, w_{2jj+1})
            const float2 w1 = s1[jj];
            const float2 w2 = s2[jj];
            const float2 w3 = s3[jj];
            const ull xaA = xin[(2 * jj + 0) * (DD / 2)];      // LDG.128 halves
            const ull xaB = xin[(2 * jj + 0) * (DD / 2) + 1];
            const ull xbA = xin[(2 * jj + 1) * (DD / 2)];
            const ull xbB = xin[(2 * jj + 1) * (DD / 2) + 1];
            {
                const ull dx = dup_f32(w0.x), dy = dup_f32(w0.y);
                accA[0] = fma2(dx, xaA, accA[0]); accB[0] = fma2(dx, xaB, accB[0]);
                accA[0] = fma2(dy, xbA, accA[0]); accB[0] = fma2(dy, xbB, accB[0]);
            }
            {
                const ull dx = dup_f32(w1.x), dy = dup_f32(w1.y);
                accA[1] = fma2(dx, xaA, accA[1]); accB[1] = fma2(dx, xaB, accB[1]);
                accA[1] = fma2(dy, xbA, accA[1]); accB[1] = fma2(dy, xbB, accB[1]);
            }
            {
                const ull dx = dup_f32(w2.x), dy = dup_f32(w2.y);
                accA[2] = fma2(dx, xaA, accA[2]); accB[2] = fma2(dx, xaB, accB[2]);
                accA[2] = fma2(dy, xbA, accA[2]); accB[2] = fma2(dy, xbB, accB[2]);
            }
            {
                const ull dx = dup_f32(w3.x), dy = dup_f32(w3.y);
                accA[3] = fma2(dx, xaA, accA[3]); accB[3] = fma2(dx, xaB, accB[3]);
                accA[3] = fma2(dy, xbA, accA[3]); accB[3] = fma2(dy, xbB, accB[3]);
            }
        }
        if (cjc < 4) {
#pragma unroll
            for (int i = 0; i < 4; i++) {
                *(ull*)&u.red[cjc][ig][i][lane << 2]       = accA[i];
                *(ull*)&u.red[cjc][ig][i][(lane << 2) + 2] = accB[i];
            }
        }
        __syncthreads();
        if (cjc >= 4) {
            const int c = cjc - 4;
#pragma unroll
            for (int i = 0; i < 4; i++) {
                ull* pA = (ull*)&u.red[c][ig][i][lane << 2];
                ull* pB = (ull*)&u.red[c][ig][i][(lane << 2) + 2];
                *pA = fma2(accA[i], ONE2, *pA);   // acc*1 + prev
                *pB = fma2(accB[i], ONE2, *pB);
            }
        }
    }
    __syncthreads();

    // ---- Phase 4b: final 4-way sum + store (one warp per i-row) ----
    if (w < 8) {
        const int r  = w;
        const int gg = r >> 2;
        const int ir = r & 3;
        const float4 v0 = *(const float4*)&u.red[0][gg][ir][lane << 2];
        const float4 v1 = *(const float4*)&u.red[1][gg][ir][lane << 2];
        const float4 v2 = *(const float4*)&u.red[2][gg][ir][lane << 2];
        const float4 v3 = *(const float4*)&u.red[3][gg][ir][lane << 2];
        float4 o;
        o.x = (v0.x + v1.x) + (v2.x + v3.x);
        o.y = (v0.y + v1.y) + (v2.y + v3.y);
        o.z = (v0.z + v1.z) + (v2.z + v3.z);
        o.w = (v0.w + v1.w) + (v2.w + v3.w);
        *(float4*)&out[((size_t)b * LL + i0 + r) * DD + (lane << 2)] = o;
    }
}

// ---------------------------------------------------------------------------
extern "C" void kernel_launch(void* const* d_in, const int* in_sizes, int n_in,
                              void* d_out, int out_size)
{
    const float* inp = (const float*)d_in[0];
    const float* uw  = (const float*)d_in[1];
    const float* vw  = (const float*)d_in[2];
    const float* aw  = (const float*)d_in[3];

    float* out  = (float*)d_out;
    float* attn = out + BB * LL * DD;

    proj_kernel<<<BB * (LL / 32), 512>>>(inp, uw, vw);
    attn_kernel<<<BB * (LL / 8), 512>>>(inp, aw, out, attn);
}

// round 17
// speedup vs baseline: 1.0429x; 1.0429x over previous
#include <cuda_runtime.h>

#define BB 8
#define LL 512
#define DD 128

typedef unsigned long long ull;

// Scratch (allocation-free rule: __device__ globals)
__device__ float g_eq[BB * DD * LL];  // [b][d][l]  e^{2q}, l contiguous
__device__ float g_ek[BB * LL * DD];  // [b][l][d]  e^{2k}

// ---- packed f32x2 helpers (sm_100a) ----
__device__ __forceinline__ ull fma2(ull a, ull b, ull c) {
    ull d; asm("fma.rn.f32x2 %0, %1, %2, %3;" : "=l"(d) : "l"(a), "l"(b), "l"(c)); return d;
}
__device__ __forceinline__ ull mul2(ull a, ull b) {
    ull d; asm("mul.rn.f32x2 %0, %1, %2;" : "=l"(d) : "l"(a), "l"(b)); return d;
}
__device__ __forceinline__ ull rcp2(ull x) {   // rcp of both packed halves
    ull y;
    asm("{\n\t.reg .f32 lo, hi;\n\t"
        "mov.b64 {lo, hi}, %1;\n\t"
        "rcp.approx.f32 lo, lo;\n\t"
        "rcp.approx.f32 hi, hi;\n\t"
        "mov.b64 %0, {lo, hi};\n\t}"
        : "=l"(y) : "l"(x));
    return y;
}
__device__ __forceinline__ ull dup_f32(float v) {
    ull d; asm("mov.b64 %0, {%1, %1};" : "=l"(d) : "f"(v)); return d;
}
__device__ __forceinline__ void unpack_f32(ull v, float& lo, float& hi) {
    asm("mov.b64 {%0, %1}, %2;" : "=f"(lo), "=f"(hi) : "l"(v));
}

#define ONE2 0x3F8000003F800000ULL

// ---------------------------------------------------------------------------
// Kernel A: Eq = exp(2 * inp@u_w^T) stored transposed [b][d][l],
//           Ek = exp(2 * inp@v_w^T) row-major [b][l][d]
// Packed over e-pairs: weights staged TRANSPOSED wuT[d][e] (pad 130) so
// (wu[e], wu[e+1]) is one LDS.64; x dup'd once per d.
// Inner step: 16 instrs / 32 MACs (vs 26 scalar).
// ---------------------------------------------------------------------------
__global__ __launch_bounds__(512, 2) void proj_kernel(
    const float* __restrict__ inp,
    const float* __restrict__ uw,
    const float* __restrict__ vw)
{
    __shared__ float xS[32][32];         // [l][d] per chunk
    __shared__ float wuT[32][130];       // [d][e], even pad -> aligned float2
    __shared__ float wvT[32][130];

    const int b    = blockIdx.x >> 4;
    const int l0   = (blockIdx.x & 15) << 5;   // 32 rows per block
    const int t    = threadIdx.x;
    const int lane = t & 31;
    const int warp = t >> 5;
    const int lrow = warp << 1;                // 2 rows per thread (16 warps)

    ull qacc2[2][2], kacc2[2][2];
#pragma unroll
    for (int i = 0; i < 2; i++)
#pragma unroll
        for (int jj = 0; jj < 2; jj++) { qacc2[i][jj] = 0ULL; kacc2[i][jj] = 0ULL; }

    for (int kc = 0; kc < 4; kc++) {
        const int d0 = kc << 5;
        // x staging: coalesced (warp reads 128B rows of inp)
        for (int idx = t; idx < 32 * 32; idx += 512) {
            const int l = idx >> 5, d = idx & 31;
            xS[l][d] = inp[(b * LL + l0 + l) * DD + d0 + d];
        }
        // weight staging: coalesced gmem read (consecutive d), transposed write
        for (int idx = t; idx < 128 * 32; idx += 512) {
            const int e = idx >> 5, d = idx & 31;
            wuT[d][e] = uw[e * DD + d0 + d];
            wvT[d][e] = vw[e * DD + d0 + d];
        }
        __syncthreads();

#pragma unroll 8
        for (int d = 0; d < 32; d++) {
            const ull X0 = dup_f32(xS[lrow + 0][d]);   // broadcast LDS + dup
            const ull X1 = dup_f32(xS[lrow + 1][d]);
#pragma unroll
            for (int jj = 0; jj < 2; jj++) {
                const int ep = (jj << 6) + (lane << 1);       // e-pair base
                const ull wu2 = *(const ull*)&wuT[d][ep];     // LDS.64, no conflict
                const ull wv2 = *(const ull*)&wvT[d][ep];
                qacc2[0][jj] = fma2(X0, wu2, qacc2[0][jj]);
                qacc2[1][jj] = fma2(X1, wu2, qacc2[1][jj]);
                kacc2[0][jj] = fma2(X0, wv2, kacc2[0][jj]);
                kacc2[1][jj] = fma2(X1, wv2, kacc2[1][jj]);
            }
        }
        __syncthreads();
    }

#pragma unroll
    for (int jj = 0; jj < 2; jj++) {
        const int e0 = (jj << 6) + (lane << 1);
#pragma unroll
        for (int i = 0; i < 2; i++) {
            const int l = l0 + lrow + i;
            float qa, qb; unpack_f32(qacc2[i][jj], qa, qb);
            g_eq[((size_t)b * DD + e0)     * LL + l] = __expf(2.0f * qa);
            g_eq[((size_t)b * DD + e0 + 1) * LL + l] = __expf(2.0f * qb);
            float ka, kb; unpack_f32(kacc2[i][jj], ka, kb);
            float2 kv = make_float2(__expf(2.0f * ka), __expf(2.0f * kb));
            *(float2*)&g_ek[((size_t)b * LL + l) * DD + e0] = kv;   // coalesced
        }
    }
}

// ---------------------------------------------------------------------------
// Kernel B (exact R14 winner): fused score + softmax + attn-write + out GEMM.
// Phase 2: packed f32x2 over j-pairs, ONE rcp per FOUR d's (quad combine).
// Phase 4: packed f32x2 over d, 2x-dedup inp reads.
// ---------------------------------------------------------------------------
__global__ __launch_bounds__(512, 2) void attn_kernel(
    const float* __restrict__ inp,
    const float* __restrict__ aw,
    float* __restrict__ out,
    float* __restrict__ attn)
{
    union U {
        struct {                        // alive through phase 3
            ulonglong2 ekD[8][64];      // Ek dup'd: [ii][d/2] = (dup d, dup d+1)
            ulonglong2 naD[64];         // -a dup'd pairs
            float scp1[8][512];         // h=1 partial scores
        } p2;
        float red[4][2][4][DD];         // phase 4 partials (overlays p2)
    };
    __shared__ __align__(16) U u;
    __shared__ float sc[8][512];        // h=0 partials -> attn weights

    const int b    = blockIdx.x >> 6;
    const int i0   = (blockIdx.x & 63) << 3;
    const int t    = threadIdx.x;
    const int lane = t & 31;
    const int w    = t >> 5;

    // Stage Ek (duplicated pairs) and -a (duplicated pairs)
    {
        const float* __restrict__ ekbase = g_ek + ((size_t)b * LL + i0) * DD;
        for (int idx = t; idx < 8 * 64; idx += 512) {
            const int ii = idx >> 6, dp = idx & 63;
            const float2 kv = *(const float2*)(ekbase + ii * DD + (dp << 1));
            u.p2.ekD[ii][dp] = make_ulonglong2(dup_f32(kv.x), dup_f32(kv.y));
        }
    }
    if (t < 64) {
        const float2 a2 = ((const float2*)aw)[t];
        u.p2.naD[t] = make_ulonglong2(dup_f32(-a2.x), dup_f32(-a2.y));
    }
    __syncthreads();

    // ---- Phase 2: partial -sum_d a_d/(Eq*Ek+1) over this warp's d-half ----
    const int h     = w >> 3;            // d-half
    const int jc    = w & 7;             // 64-j tile
    const int jb    = jc << 6;
    const int dbase = h << 6;

    ull acc2[8];
#pragma unroll
    for (int ii = 0; ii < 8; ii++) acc2[ii] = 0ULL;

    // float2 view of g_eq: row d has LL/2 float2s; lane owns pair (jb+2*lane)
    const float2* __restrict__ eqp2 =
        (const float2*)g_eq + (size_t)b * DD * (LL >> 1) + (jb >> 1) + lane;

#pragma unroll 2
    for (int p = 0; p < 16; p++) {
        const int d0 = dbase + (p << 2);
        const ull eqA = *(const ull*)(eqp2 + (size_t)(d0 + 0) * (LL >> 1));
        const ull eqB = *(const ull*)(eqp2 + (size_t)(d0 + 1) * (LL >> 1));
        const ull eqC = *(const ull*)(eqp2 + (size_t)(d0 + 2) * (LL >> 1));
        const ull eqD = *(const ull*)(eqp2 + (size_t)(d0 + 3) * (LL >> 1));
        const ulonglong2 naAB = u.p2.naD[(d0 >> 1) + 0];   // LDS.128 broadcast
        const ulonglong2 naCD = u.p2.naD[(d0 >> 1) + 1];
#pragma unroll
        for (int ii = 0; ii < 8; ii++) {
            const ulonglong2 ekAB = u.p2.ekD[ii][(d0 >> 1) + 0];  // LDS.128
            const ulonglong2 ekCD = u.p2.ekD[ii][(d0 >> 1) + 1];
            const ull x1 = fma2(eqA, ekAB.x, ONE2);
            const ull x2 = fma2(eqB, ekAB.y, ONE2);
            const ull x3 = fma2(eqC, ekCD.x, ONE2);
            const ull x4 = fma2(eqD, ekCD.y, ONE2);
            // pair numerators (carry -a) and pair denominators
            ull t1 = mul2(naAB.x, x2); t1 = fma2(naAB.y, x1, t1);
            ull t2 = mul2(naCD.x, x4); t2 = fma2(naCD.y, x3, t2);
            const ull p12 = mul2(x1, x2);
            const ull p34 = mul2(x3, x4);
            // quad combine: one rcp per 4 d's
            ull num = mul2(t1, p34); num = fma2(t2, p12, num);
            const ull den = mul2(p12, p34);
            const ull r   = rcp2(den);
            acc2[ii] = fma2(num, r, acc2[ii]);
        }
    }
    {
        float (* __restrict__ dst)[512] = (h == 0) ? sc : u.p2.scp1;
        const int j = jb + (lane << 1);
#pragma unroll
        for (int ii = 0; ii < 8; ii++)
            *(ull*)&dst[ii][j] = acc2[ii];    // STS.64, (j, j+1) adjacent
    }
    __syncthreads();

    // ---- Phase 3: softmax over j (score = 2*(sc + scp1) + const) ----
    if (w < 8) {
        const int r = w;
        float v[16];
        float mx = -1e30f;
#pragma unroll
        for (int q = 0; q < 16; q++) {
            const int jj = lane + (q << 5);
            v[q] = 2.0f * (sc[r][jj] + u.p2.scp1[r][jj]);
            mx = fmaxf(mx, v[q]);
        }
#pragma unroll
        for (int o = 16; o > 0; o >>= 1) mx = fmaxf(mx, __shfl_xor_sync(0xffffffffu, mx, o));
        float s = 0.f;
#pragma unroll
        for (int q = 0; q < 16; q++) { v[q] = __expf(v[q] - mx); s += v[q]; }
#pragma unroll
        for (int o = 16; o > 0; o >>= 1) s += __shfl_xor_sync(0xffffffffu, s, o);
        const float inv = 1.0f / s;
        float* arow = attn + ((size_t)b * LL + i0 + r) * LL;
#pragma unroll
        for (int q = 0; q < 16; q++) {
            const int jj = lane + (q << 5);
            const float av = v[q] * inv;
            sc[r][jj] = av;       // reuse for phase 4
            arow[jj]  = av;       // coalesced attn output
        }
    }
    __syncthreads();   // scp1/staging dead beyond this point -> red may overlay

    // ---- Phase 4a: packed-d partial out over 64 j's for 4 i-rows per warp --
    const int ig = w >> 3;   // i-group: rows ig*4 .. ig*4+3
    const int cjc = w & 7;   // j-chunk: [cjc*64, cjc*64+64)
    {
        ull accA[4], accB[4];  // per i-row: (d0,d1) and (d2,d3) of lane's 4 d's
#pragma unroll
        for (int i = 0; i < 4; i++) { accA[i] = 0ULL; accB[i] = 0ULL; }

        const ull* __restrict__ xin =
            (const ull*)(inp + ((size_t)b * LL + (cjc << 6)) * DD) + (lane << 1);
        const float2* __restrict__ s0 = (const float2*)&sc[(ig << 2) + 0][cjc << 6];
        const float2* __restrict__ s1 = (const float2*)&sc[(ig << 2) + 1][cjc << 6];
        const float2* __restrict__ s2 = (const float2*)&sc[(ig << 2) + 2][cjc << 6];
        const float2* __restrict__ s3 = (const float2*)&sc[(ig << 2) + 3][cjc << 6];
#pragma unroll 4
        for (int jj = 0; jj < 32; jj++) {
            const float2 w0 = s0[jj];               // (w_{2jj}, w_{2jj+1})
            const float2 w1 = s1[jj];
            const float2 w2 = s2[jj];
            const float2 w3 = s3[jj];
            const ull xaA = xin[(2 * jj + 0) * (DD / 2)];      // LDG.128 halves
            const ull xaB = xin[(2 * jj + 0) * (DD / 2) + 1];
            const ull xbA = xin[(2 * jj + 1) * (DD / 2)];
            const ull xbB = xin[(2 * jj + 1) * (DD / 2) + 1];
            {
                const ull dx = dup_f32(w0.x), dy = dup_f32(w0.y);
                accA[0] = fma2(dx, xaA, accA[0]); accB[0] = fma2(dx, xaB, accB[0]);
                accA[0] = fma2(dy, xbA, accA[0]); accB[0] = fma2(dy, xbB, accB[0]);
            }
            {
                const ull dx = dup_f32(w1.x), dy = dup_f32(w1.y);
                accA[1] = fma2(dx, xaA, accA[1]); accB[1] = fma2(dx, xaB, accB[1]);
                accA[1] = fma2(dy, xbA, accA[1]); accB[1] = fma2(dy, xbB, accB[1]);
            }
            {
                const ull dx = dup_f32(w2.x), dy = dup_f32(w2.y);
                accA[2] = fma2(dx, xaA, accA[2]); accB[2] = fma2(dx, xaB, accB[2]);
                accA[2] = fma2(dy, xbA, accA[2]); accB[2] = fma2(dy, xbB, accB[2]);
            }
            {
                const ull dx = dup_f32(w3.x), dy = dup_f32(w3.y);
                accA[3] = fma2(dx, xaA, accA[3]); accB[3] = fma2(dx, xaB, accB[3]);
                accA[3] = fma2(dy, xbA, accA[3]); accB[3] = fma2(dy, xbB, accB[3]);
            }
        }
        if (cjc < 4) {
#pragma unroll
            for (int i = 0; i < 4; i++) {
                *(ull*)&u.red[cjc][ig][i][lane << 2]       = accA[i];
                *(ull*)&u.red[cjc][ig][i][(lane << 2) + 2] = accB[i];
            }
        }
        __syncthreads();
        if (cjc >= 4) {
            const int c = cjc - 4;
#pragma unroll
            for (int i = 0; i < 4; i++) {
                ull* pA = (ull*)&u.red[c][ig][i][lane << 2];
                ull* pB = (ull*)&u.red[c][ig][i][(lane << 2) + 2];
                *pA = fma2(accA[i], ONE2, *pA);   // acc*1 + prev
                *pB = fma2(accB[i], ONE2, *pB);
            }
        }
    }
    __syncthreads();

    // ---- Phase 4b: final 4-way sum + store (one warp per i-row) ----
    if (w < 8) {
        const int r  = w;
        const int gg = r >> 2;
        const int ir = r & 3;
        const float4 v0 = *(const float4*)&u.red[0][gg][ir][lane << 2];
        const float4 v1 = *(const float4*)&u.red[1][gg][ir][lane << 2];
        const float4 v2 = *(const float4*)&u.red[2][gg][ir][lane << 2];
        const float4 v3 = *(const float4*)&u.red[3][gg][ir][lane << 2];
        float4 o;
        o.x = (v0.x + v1.x) + (v2.x + v3.x);
        o.y = (v0.y + v1.y) + (v2.y + v3.y);
        o.z = (v0.z + v1.z) + (v2.z + v3.z);
        o.w = (v0.w + v1.w) + (v2.w + v3.w);
        *(float4*)&out[((size_t)b * LL + i0 + r) * DD + (lane << 2)] = o;
    }
}

// ---------------------------------------------------------------------------
extern "C" void kernel_launch(void* const* d_in, const int* in_sizes, int n_in,
                              void* d_out, int out_size)
{
    const float* inp = (const float*)d_in[0];
    const float* uw  = (const float*)d_in[1];
    const float* vw  = (const float*)d_in[2];
    const float* aw  = (const float*)d_in[3];

    float* out  = (float*)d_out;
    float* attn = out + BB * LL * DD;

    proj_kernel<<<BB * (LL / 32), 512>>>(inp, uw, vw);
    attn_kernel<<<BB * (LL / 8), 512>>>(inp, aw, out, attn);
}